// round 5
// baseline (speedup 1.0000x reference)
#include <cuda_runtime.h>
#include <math.h>

#define BATCH  64
#define LSUB   512
#define SWORDS 512
#define HID    768
#define NC     9
#define NWORDS (BATCH * SWORDS)
#define MGRID  512          // main grid: 512 blocks x 8 warps x 4 pairs = 16384 pairs

typedef unsigned long long u64;

__device__ float g_Wt[NC * HID];      // transposed W: g_Wt[c*HID + h]
__device__ int   g_starts[NWORDS];
__device__ float g_loss;
__device__ int   g_cnt;
__device__ int   g_done;

__device__ __forceinline__ u64 fma2(u64 a, u64 b, u64 c) {
    u64 d; asm("fma.rn.f32x2 %0,%1,%2,%3;" : "=l"(d) : "l"(a), "l"(b), "l"(c)); return d;
}
__device__ __forceinline__ u64 add2(u64 a, u64 b) {
    u64 d; asm("add.rn.f32x2 %0,%1,%2;" : "=l"(d) : "l"(a), "l"(b)); return d;
}
__device__ __forceinline__ float upk_sum(u64 v) {
    float lo, hi; asm("mov.b64 {%0,%1},%2;" : "=f"(lo), "=f"(hi) : "l"(v)); return lo + hi;
}

// ---------------------------------------------------------------------------
// Setup: 64 blocks x 256 threads. Block b scans batch b's ids_lens into
// g_starts, and transposes its 12-row slice of W into g_Wt. Block 0 resets
// the global accumulators.
// ---------------------------------------------------------------------------
__global__ void __launch_bounds__(256) setup_kernel(
    const int* __restrict__ ids_lens, const float* __restrict__ W)
{
    __shared__ int s_wsum[8];
    const int b = blockIdx.x, tid = threadIdx.x;
    const int lane = tid & 31, warp = tid >> 5;

    int2 lp = ((const int2*)(ids_lens + b * SWORDS))[tid];
    int sum2 = lp.x + lp.y;
    int inc = sum2;
#pragma unroll
    for (int off = 1; off < 32; off <<= 1) {
        int n = __shfl_up_sync(0xffffffffu, inc, off);
        if (lane >= off) inc += n;
    }
    int lane_ex = inc - sum2;
    if (lane == 31) s_wsum[warp] = inc;
    __syncthreads();
    int wbase = 0;
#pragma unroll
    for (int i = 0; i < 8; i++) if (i < warp) wbase += s_wsum[i];
    int ex0 = wbase + lane_ex;
    int base = b * SWORDS + 2 * tid;
    g_starts[base]     = ex0;
    g_starts[base + 1] = ex0 + lp.x;

    // W transpose slice: rows [b*12, (b+1)*12)
    if (tid < 12 * NC) {
        int h = b * 12 + tid / NC;
        int c = tid - (tid / NC) * NC;
        g_Wt[c * HID + h] = W[h * NC + c];
    }
    if (b == 0 && tid == 0) { g_loss = 0.0f; g_cnt = 0; g_done = 0; }
}

// ---------------------------------------------------------------------------
// Main: 512 blocks x 256 threads, one wave. Warp q = blk*8+warp owns pairs
// [4q, 4q+4) — all within batch q>>6. Packed f32x2 dot products against
// transposed W in shared (float4 copy, no div). Last block writes out[0].
// ---------------------------------------------------------------------------
__global__ void __launch_bounds__(256) main_kernel(
    const float* __restrict__ x,        // [B, L, H]
    const float* __restrict__ bias,     // [C]
    const int*   __restrict__ ids_lens, // [B, S]
    const int*   __restrict__ label_ids,
    float*       __restrict__ out)      // out[0]=loss, out[1..]=pred
{
    __shared__ float Ws[NC * HID];      // Ws[c*HID + h]
    __shared__ float sb[NC];
    __shared__ float s_loss;
    __shared__ int   s_cnt;

    const int tid  = threadIdx.x;
    const int lane = tid & 31;
    const int warp = tid >> 5;

    // fast vector copy of pre-transposed W
    {
        const float4* src = (const float4*)g_Wt;
        float4*       dst = (float4*)Ws;
        for (int i = tid; i < (NC * HID) / 4; i += 256) dst[i] = src[i];
    }
    if (tid < NC) sb[tid] = bias[tid];
    if (tid == 0) { s_loss = 0.0f; s_cnt = 0; }
    __syncthreads();

    const int q     = blockIdx.x * 8 + warp;   // global warp id, 0..4095
    const int batch = q >> 6;                  // 64 warps per batch

    float lloss = 0.0f;
    int   lcnt  = 0;

    const ulonglong2 z2 = make_ulonglong2(0ull, 0ull);
    const int RS = HID / 4;                    // row stride in 16B chunks = 192

#pragma unroll
    for (int it = 0; it < 4; it++) {
        int p  = q * 4 + it;                   // pair index
        int w0 = 2 * p, w1 = w0 + 1;
        int len0 = ids_lens[w0], len1 = ids_lens[w1];
        int st0  = g_starts[w0], st1 = g_starts[w1];

        const ulonglong2* base0 = (const ulonglong2*)(x + ((size_t)(batch * LSUB + st0)) * HID);
        const ulonglong2* base1 = (const ulonglong2*)(x + ((size_t)(batch * LSUB + st1)) * HID);

        u64 acc0[NC], acc1[NC];
#pragma unroll
        for (int c = 0; c < NC; c++) { acc0[c] = 0ull; acc1[c] = 0ull; }

#pragma unroll
        for (int g = 0; g < 6; g++) {
            int idx = g * 32 + lane;           // 16B-chunk index within row
            ulonglong2 a0 = (len0 > 0) ? base0[idx]          : z2;
            ulonglong2 a1 = (len0 > 1) ? base0[idx + RS]     : z2;
            ulonglong2 a2 = (len0 > 2) ? base0[idx + 2 * RS] : z2;
            ulonglong2 c0 = (len1 > 0) ? base1[idx]          : z2;
            ulonglong2 c1 = (len1 > 1) ? base1[idx + RS]     : z2;
            ulonglong2 c2 = (len1 > 2) ? base1[idx + 2 * RS] : z2;

            u64 v0l = add2(a0.x, add2(a1.x, a2.x));
            u64 v0h = add2(a0.y, add2(a1.y, a2.y));
            u64 v1l = add2(c0.x, add2(c1.x, c2.x));
            u64 v1h = add2(c0.y, add2(c1.y, c2.y));

            int hb = g * 128 + lane * 4;
#pragma unroll
            for (int c = 0; c < NC; c++) {
                ulonglong2 wc = *(const ulonglong2*)&Ws[c * HID + hb];
                acc0[c] = fma2(v0l, wc.x, acc0[c]);
                acc0[c] = fma2(v0h, wc.y, acc0[c]);
                acc1[c] = fma2(v1l, wc.x, acc1[c]);
                acc1[c] = fma2(v1h, wc.y, acc1[c]);
            }
        }

        float r0[NC], r1[NC];
#pragma unroll
        for (int c = 0; c < NC; c++) { r0[c] = upk_sum(acc0[c]); r1[c] = upk_sum(acc1[c]); }
#pragma unroll
        for (int c = 0; c < NC; c++) {
#pragma unroll
            for (int off = 16; off; off >>= 1) {
                r0[c] += __shfl_xor_sync(0xffffffffu, r0[c], off);
                r1[c] += __shfl_xor_sync(0xffffffffu, r1[c], off);
            }
        }

        if (lane == 0) {
#pragma unroll
            for (int which = 0; which < 2; which++) {
                int    w   = which ? w1 : w0;
                int    len = which ? len1 : len0;
                float* a   = which ? r1 : r0;

                float inv = (len > 0) ? (1.0f / (float)len) : 0.0f;
                float lg[NC];
                float m = -1e30f; int am = 0;
#pragma unroll
                for (int c = 0; c < NC; c++) {
                    lg[c] = fmaf(a[c], inv, sb[c]);
                    if (lg[c] > m) { m = lg[c]; am = c; }
                }
                out[1 + w] = (float)am;
                if (len > 0) {
                    float sum = 0.0f;
#pragma unroll
                    for (int c = 0; c < NC; c++) sum += __expf(lg[c] - m);
                    int lab = label_ids[w];
                    lab = lab < 0 ? 0 : (lab > NC - 1 ? NC - 1 : lab);
                    lloss += -(lg[lab] - m - __logf(sum));
                    lcnt  += 1;
                }
            }
        }
    }

    if (lane == 0 && lcnt > 0) {
        atomicAdd(&s_loss, lloss);
        atomicAdd(&s_cnt, lcnt);
    }
    __syncthreads();

    if (tid == 0) {
        if (s_cnt > 0) {
            atomicAdd(&g_loss, s_loss);
            atomicAdd(&g_cnt, s_cnt);
        }
        __threadfence();
        int old = atomicAdd(&g_done, 1);
        if (old == MGRID - 1) {                 // last block finalizes
            float lv = atomicAdd(&g_loss, 0.0f);
            int   cv = atomicAdd(&g_cnt, 0);
            out[0] = lv / fmaxf((float)cv, 1.0f);
        }
    }
}

extern "C" void kernel_launch(void* const* d_in, const int* in_sizes, int n_in,
                              void* d_out, int out_size) {
    const float* bert_out  = (const float*)d_in[0];
    const float* W         = (const float*)d_in[1];
    const float* b         = (const float*)d_in[2];
    const int*   ids_lens  = (const int*)d_in[4];
    const int*   label_ids = (const int*)d_in[5];
    float* out = (float*)d_out;

    setup_kernel<<<BATCH, 256>>>(ids_lens, W);
    main_kernel<<<MGRID, 256>>>(bert_out, b, ids_lens, label_ids, out);
}

// round 6
// speedup vs baseline: 3.6774x; 3.6774x over previous
#include <cuda_runtime.h>
#include <math.h>

#define BATCH  64
#define LSUB   512
#define SWORDS 512
#define HID    768
#define NC     9
#define NWORDS (BATCH * SWORDS)
#define MGRID  296          // 2 blocks/SM, one wave
#define NPAIRS (NWORDS / 2)

typedef unsigned long long u64;

__device__ float g_Wt[NC * HID];      // transposed W: g_Wt[c*HID + h]
__device__ int   g_starts[NWORDS];
__device__ float g_loss;
__device__ int   g_cnt;
__device__ int   g_done;

__device__ __forceinline__ u64 fma2(u64 a, u64 b, u64 c) {
    u64 d; asm("fma.rn.f32x2 %0,%1,%2,%3;" : "=l"(d) : "l"(a), "l"(b), "l"(c)); return d;
}
__device__ __forceinline__ u64 add2(u64 a, u64 b) {
    u64 d; asm("add.rn.f32x2 %0,%1,%2;" : "=l"(d) : "l"(a), "l"(b)); return d;
}
__device__ __forceinline__ float upk_sum(u64 v) {
    float lo, hi; asm("mov.b64 {%0,%1},%2;" : "=f"(lo), "=f"(hi) : "l"(v)); return lo + hi;
}

// ---------------------------------------------------------------------------
// Setup: 64 blocks x 256 threads. Block b scans batch b's ids_lens into
// g_starts; transposes its 12-row slice of W; block 0 resets accumulators.
// ---------------------------------------------------------------------------
__global__ void __launch_bounds__(256) setup_kernel(
    const int* __restrict__ ids_lens, const float* __restrict__ W)
{
    __shared__ int s_wsum[8];
    const int b = blockIdx.x, tid = threadIdx.x;
    const int lane = tid & 31, warp = tid >> 5;

    int2 lp = ((const int2*)(ids_lens + b * SWORDS))[tid];
    int sum2 = lp.x + lp.y;
    int inc = sum2;
#pragma unroll
    for (int off = 1; off < 32; off <<= 1) {
        int n = __shfl_up_sync(0xffffffffu, inc, off);
        if (lane >= off) inc += n;
    }
    int lane_ex = inc - sum2;
    if (lane == 31) s_wsum[warp] = inc;
    __syncthreads();
    int wbase = 0;
#pragma unroll
    for (int i = 0; i < 8; i++) if (i < warp) wbase += s_wsum[i];
    int ex0 = wbase + lane_ex;
    int base = b * SWORDS + 2 * tid;
    g_starts[base]     = ex0;
    g_starts[base + 1] = ex0 + lp.x;

    if (tid < 12 * NC) {
        int h = b * 12 + tid / NC;
        int c = tid - (tid / NC) * NC;
        g_Wt[c * HID + h] = W[h * NC + c];
    }
    if (b == 0 && tid == 0) { g_loss = 0.0f; g_cnt = 0; g_done = 0; }
}

// ---------------------------------------------------------------------------
// Main: 296 blocks x 256 threads (2 blocks/SM, one wave). Warps grid-stride
// over 16384 word-pairs; pair loop NOT unrolled (register pressure), inner
// 6-group loop fully unrolled (MLP). Last block writes out[0].
// ---------------------------------------------------------------------------
__global__ void __launch_bounds__(256, 2) main_kernel(
    const float* __restrict__ x,        // [B, L, H]
    const float* __restrict__ bias,     // [C]
    const int*   __restrict__ ids_lens, // [B, S]
    const int*   __restrict__ label_ids,
    float*       __restrict__ out)      // out[0]=loss, out[1..]=pred
{
    __shared__ float Ws[NC * HID];      // Ws[c*HID + h]
    __shared__ float sb[NC];
    __shared__ float s_loss;
    __shared__ int   s_cnt;

    const int tid  = threadIdx.x;
    const int lane = tid & 31;
    const int warp = tid >> 5;

    {
        const float4* src = (const float4*)g_Wt;
        float4*       dst = (float4*)Ws;
        for (int i = tid; i < (NC * HID) / 4; i += 256) dst[i] = src[i];
    }
    if (tid < NC) sb[tid] = bias[tid];
    if (tid == 0) { s_loss = 0.0f; s_cnt = 0; }
    __syncthreads();

    const int gw = blockIdx.x * 8 + warp;       // global warp id
    const int nw = MGRID * 8;

    float lloss = 0.0f;
    int   lcnt  = 0;

    const ulonglong2 z2 = make_ulonglong2(0ull, 0ull);
    const int RS = HID / 4;                     // row stride in 16B chunks = 192

#pragma unroll 1
    for (int p = gw; p < NPAIRS; p += nw) {
        int w0 = 2 * p, w1 = w0 + 1;            // same batch (w0 even)
        int batch = w0 >> 9;
        int len0 = ids_lens[w0], len1 = ids_lens[w1];
        int st0  = g_starts[w0], st1 = g_starts[w1];

        const ulonglong2* base0 = (const ulonglong2*)(x + ((size_t)(batch * LSUB + st0)) * HID);
        const ulonglong2* base1 = (const ulonglong2*)(x + ((size_t)(batch * LSUB + st1)) * HID);

        u64 acc0[NC], acc1[NC];
#pragma unroll
        for (int c = 0; c < NC; c++) { acc0[c] = 0ull; acc1[c] = 0ull; }

#pragma unroll
        for (int g = 0; g < 6; g++) {
            int idx = g * 32 + lane;            // 16B-chunk index within row
            ulonglong2 a0 = (len0 > 0) ? base0[idx]          : z2;
            ulonglong2 a1 = (len0 > 1) ? base0[idx + RS]     : z2;
            ulonglong2 a2 = (len0 > 2) ? base0[idx + 2 * RS] : z2;
            ulonglong2 c0 = (len1 > 0) ? base1[idx]          : z2;
            ulonglong2 c1 = (len1 > 1) ? base1[idx + RS]     : z2;
            ulonglong2 c2 = (len1 > 2) ? base1[idx + 2 * RS] : z2;

            u64 v0l = add2(a0.x, add2(a1.x, a2.x));
            u64 v0h = add2(a0.y, add2(a1.y, a2.y));
            u64 v1l = add2(c0.x, add2(c1.x, c2.x));
            u64 v1h = add2(c0.y, add2(c1.y, c2.y));

            int hb = g * 128 + lane * 4;
#pragma unroll
            for (int c = 0; c < NC; c++) {
                ulonglong2 wc = *(const ulonglong2*)&Ws[c * HID + hb];
                acc0[c] = fma2(v0l, wc.x, acc0[c]);
                acc0[c] = fma2(v0h, wc.y, acc0[c]);
                acc1[c] = fma2(v1l, wc.x, acc1[c]);
                acc1[c] = fma2(v1h, wc.y, acc1[c]);
            }
        }

        float r0[NC], r1[NC];
#pragma unroll
        for (int c = 0; c < NC; c++) { r0[c] = upk_sum(acc0[c]); r1[c] = upk_sum(acc1[c]); }
#pragma unroll
        for (int c = 0; c < NC; c++) {
#pragma unroll
            for (int off = 16; off; off >>= 1) {
                r0[c] += __shfl_xor_sync(0xffffffffu, r0[c], off);
                r1[c] += __shfl_xor_sync(0xffffffffu, r1[c], off);
            }
        }

        if (lane == 0) {
#pragma unroll
            for (int which = 0; which < 2; which++) {
                int    w   = which ? w1 : w0;
                int    len = which ? len1 : len0;
                float* a   = which ? r1 : r0;

                float inv = (len > 0) ? (1.0f / (float)len) : 0.0f;
                float lg[NC];
                float m = -1e30f; int am = 0;
#pragma unroll
                for (int c = 0; c < NC; c++) {
                    lg[c] = fmaf(a[c], inv, sb[c]);
                    if (lg[c] > m) { m = lg[c]; am = c; }
                }
                out[1 + w] = (float)am;
                if (len > 0) {
                    float sum = 0.0f;
#pragma unroll
                    for (int c = 0; c < NC; c++) sum += __expf(lg[c] - m);
                    int lab = label_ids[w];
                    lab = lab < 0 ? 0 : (lab > NC - 1 ? NC - 1 : lab);
                    lloss += -(lg[lab] - m - __logf(sum));
                    lcnt  += 1;
                }
            }
        }
    }

    if (lane == 0 && lcnt > 0) {
        atomicAdd(&s_loss, lloss);
        atomicAdd(&s_cnt, lcnt);
    }
    __syncthreads();

    if (tid == 0) {
        if (s_cnt > 0) {
            atomicAdd(&g_loss, s_loss);
            atomicAdd(&g_cnt, s_cnt);
        }
        __threadfence();
        int old = atomicAdd(&g_done, 1);
        if (old == MGRID - 1) {                 // last block finalizes
            float lv = atomicAdd(&g_loss, 0.0f);
            int   cv = atomicAdd(&g_cnt, 0);
            out[0] = lv / fmaxf((float)cv, 1.0f);
        }
    }
}

extern "C" void kernel_launch(void* const* d_in, const int* in_sizes, int n_in,
                              void* d_out, int out_size) {
    const float* bert_out  = (const float*)d_in[0];
    const float* W         = (const float*)d_in[1];
    const float* b         = (const float*)d_in[2];
    const int*   ids_lens  = (const int*)d_in[4];
    const int*   label_ids = (const int*)d_in[5];
    float* out = (float*)d_out;

    setup_kernel<<<BATCH, 256>>>(ids_lens, W);
    main_kernel<<<MGRID, 256>>>(bert_out, b, ids_lens, label_ids, out);
}